// round 7
// baseline (speedup 1.0000x reference)
#include <cuda_runtime.h>

#define NN 50000
#define FF 64
#define HIDN 32
#define TT 8
#define EE 800000
#define PP 800000

// ---------------- persistent scratch (static device arrays) ------------------
// All N x 128 tensors use gate-permuted column layout: col = h*4 + g
// so a float4 at h*4 holds (i,f,c,o) pre-acts / weights for hidden unit h.
__device__ float g_Y1[(size_t)NN * 128];
__device__ float g_Y2[(size_t)NN * 128];
__device__ float g_Z0[(size_t)NN * 128];
__device__ float g_V1[(size_t)NN * 128];
__device__ float g_V2[(size_t)NN * 128];
__device__ float g_H[(size_t)NN * 32];
__device__ float g_C[(size_t)NN * 32];
__device__ float g_h1[(size_t)NN * 16];

__device__ int   g_deg8[TT * NN];
__device__ int   g_hist8[TT * NN];
__device__ int   g_fill8[TT * NN];
__device__ int   g_cs8[TT * (NN + 1)];
__device__ float g_dis8[TT * NN];
__device__ int   g_erow8[(size_t)TT * EE];
__device__ float g_enorm8[(size_t)TT * EE];

// folded weights (gate-permuted columns)
__device__ float g_A0[32 * 128];   // Wh0 - Wh2
__device__ float g_A1[32 * 128];   // Wh1
__device__ float g_A2[32 * 128];   // Wh2
__device__ float g_W03p[64 * 128]; // Wx0 - Wx2
__device__ float g_W1p[64 * 128];  // Wx1
__device__ float g_W2p[64 * 128];  // Wx2
__device__ float g_biasp[128];     // bx + bh + b_gate

__device__ __forceinline__ float sigm(float v) { return 1.0f / (1.0f + expf(-v)); }

__device__ __forceinline__ float4 f4add(float4 a, float4 b) {
    return make_float4(a.x + b.x, a.y + b.y, a.z + b.z, a.w + b.w);
}
__device__ __forceinline__ float4 f4fma(float s, float4 a, float4 acc) {
    acc.x += s * a.x; acc.y += s * a.y; acc.z += s * a.z; acc.w += s * a.w;
    return acc;
}

// ---------------- weight folding --------------------------------------------
__global__ void build_weights(const float* __restrict__ Wx, const float* __restrict__ bx,
                              const float* __restrict__ Wh, const float* __restrict__ bh,
                              const float* __restrict__ bg) {
    int idx = blockIdx.x * blockDim.x + threadIdx.x;
    if (idx < 12288) {                         // A0 / A1 / A2 : 32 x 128 each
        int m = idx >> 12;                     // which matrix
        int r = (idx >> 7) & 31;               // k row
        int c = idx & 127;
        int h = c >> 2, g = c & 3;
        float v;
        if (m == 0)      v = Wh[((g * 3 + 0) * 32 + r) * 32 + h]
                           - Wh[((g * 3 + 2) * 32 + r) * 32 + h];
        else if (m == 1) v = Wh[((g * 3 + 1) * 32 + r) * 32 + h];
        else             v = Wh[((g * 3 + 2) * 32 + r) * 32 + h];
        if (m == 0) g_A0[(idx & 4095)] = v;
        else if (m == 1) g_A1[(idx & 4095)] = v;
        else g_A2[(idx & 4095)] = v;
    } else if (idx < 12288 + 3 * 8192) {       // W03p / W1p / W2p : 64 x 128
        int base = idx - 12288;
        int m = base >> 13;
        int f = (base >> 7) & 63;
        int c = base & 127;
        int h = c >> 2, g = c & 3;
        float v;
        if (m == 0)      v = Wx[((g * 3 + 0) * 64 + f) * 32 + h]
                           - Wx[((g * 3 + 2) * 64 + f) * 32 + h];
        else if (m == 1) v = Wx[((g * 3 + 1) * 64 + f) * 32 + h];
        else             v = Wx[((g * 3 + 2) * 64 + f) * 32 + h];
        int o = f * 128 + c;
        if (m == 0) g_W03p[o] = v;
        else if (m == 1) g_W1p[o] = v;
        else g_W2p[o] = v;
    } else if (idx < 12288 + 3 * 8192 + 128) { // biasp
        int c = idx - 12288 - 3 * 8192;
        int h = c >> 2, g = c & 3;
        g_biasp[c] = bx[g * 32 + h] + bh[g * 32 + h] + bg[g * 32 + h];
    }
}

__global__ void zero_state() {
    int idx = blockIdx.x * blockDim.x + threadIdx.x;
    if (idx < NN * 32) { g_H[idx] = 0.0f; g_C[idx] = 0.0f; }
    if (idx < TT * NN) { g_deg8[idx] = 0; g_hist8[idx] = 0; g_fill8[idx] = 0; }
}

// ---------------- CSC build for all 8 snapshots ------------------------------
__global__ void histogram8(const int* __restrict__ eidx) {
    long long i = (long long)blockIdx.x * blockDim.x + threadIdx.x;
    if (i < (long long)TT * EE) {
        int t = (int)(i / EE), e = (int)(i % EE);
        const int* row = eidx + (size_t)t * 2 * EE;
        const int* col = row + EE;
        atomicAdd(&g_deg8[t * NN + row[e]], 1);
        atomicAdd(&g_hist8[t * NN + col[e]], 1);
    }
}

__global__ void dis8_kernel() {
    int i = blockIdx.x * blockDim.x + threadIdx.x;
    if (i < TT * NN) {
        int d = g_deg8[i];
        g_dis8[i] = (d > 0) ? rsqrtf((float)d) : 0.0f;
    }
}

// one block per step; scans its 50000-entry histogram
__global__ void scan8() {
    __shared__ int sh[1024];
    __shared__ int stotal;
    int t = blockIdx.x;
    const int* hist = g_hist8 + t * NN;
    int* cs = g_cs8 + t * (NN + 1);
    int tid = threadIdx.x;
    if (tid == 0) stotal = 0;
    __syncthreads();
    for (int base = 0; base < NN; base += 1024) {
        int i = base + tid;
        int v = (i < NN) ? hist[i] : 0;
        sh[tid] = v;
        __syncthreads();
        for (int off = 1; off < 1024; off <<= 1) {
            int tv = 0;
            if (tid >= off) tv = sh[tid - off];
            __syncthreads();
            sh[tid] += tv;
            __syncthreads();
        }
        if (i < NN) cs[i] = stotal + sh[tid] - v;
        __syncthreads();
        if (tid == 0) stotal += sh[1023];
        __syncthreads();
    }
    if (tid == 0) cs[NN] = stotal;
}

__global__ void scatter8(const int* __restrict__ eidx) {
    long long i = (long long)blockIdx.x * blockDim.x + threadIdx.x;
    if (i < (long long)TT * EE) {
        int t = (int)(i / EE), e = (int)(i % EE);
        const int* row = eidx + (size_t)t * 2 * EE;
        const int* col = row + EE;
        int r = row[e], c = col[e];
        int pos = g_cs8[t * (NN + 1) + c] + atomicAdd(&g_fill8[t * NN + c], 1);
        g_erow8[(size_t)t * EE + pos] = r;
        g_enorm8[(size_t)t * EE + pos] = -g_dis8[t * NN + r] * g_dis8[t * NN + c];
    }
}

// ---------------- init GEMM: out[N,128] = x[N,64] @ Bw[64,128] (+bias) -------
__global__ void gemm_init(const float* __restrict__ x, const float* __restrict__ Bw,
                          const float* __restrict__ bias, float* __restrict__ out) {
    __shared__ float As[8][64];
    __shared__ float Bs[8][128];
    int bm = blockIdx.x * 64;
    int tid = threadIdx.x;
    int tcol = tid & 15;
    int trow = tid >> 4;
    float acc[4][8];
#pragma unroll
    for (int i = 0; i < 4; i++)
#pragma unroll
        for (int j = 0; j < 8; j++) acc[i][j] = 0.0f;

    for (int k0 = 0; k0 < 64; k0 += 8) {
#pragma unroll
        for (int i = 0; i < 2; i++) {
            int idx = tid + i * 256;
            int m = idx >> 3, k = idx & 7;
            int row = bm + m;
            As[k][m] = (row < NN) ? x[(size_t)row * 64 + k0 + k] : 0.0f;
        }
#pragma unroll
        for (int i = 0; i < 4; i++) {
            int idx = tid + i * 256;
            int k = idx >> 7, n = idx & 127;
            Bs[k][n] = Bw[(size_t)(k0 + k) * 128 + n];
        }
        __syncthreads();
#pragma unroll
        for (int k = 0; k < 8; k++) {
            float a[4], b[8];
#pragma unroll
            for (int i = 0; i < 4; i++) a[i] = As[k][trow * 4 + i];
#pragma unroll
            for (int j = 0; j < 8; j++) b[j] = Bs[k][tcol * 8 + j];
#pragma unroll
            for (int i = 0; i < 4; i++)
#pragma unroll
                for (int j = 0; j < 8; j++) acc[i][j] += a[i] * b[j];
        }
        __syncthreads();
    }
#pragma unroll
    for (int i = 0; i < 4; i++) {
        int row = bm + trow * 4 + i;
        if (row < NN) {
#pragma unroll
            for (int j = 0; j < 8; j++) {
                int n = tcol * 8 + j;
                float v = acc[i][j];
                if (bias) v += bias[n];
                out[(size_t)row * 128 + n] = v;
            }
        }
    }
}

// ---------------- fused step kernels -----------------------------------------
// Kernel A: U2 = L @ V2src ; V1 = Y1 + H@A1 + 2*U2
__global__ void stepA(int t, const float* __restrict__ V2src) {
    __shared__ float sA1[32 * 128];
    int tid = threadIdx.x;
    for (int i = tid; i < 32 * 128; i += 256) sA1[i] = g_A1[i];
    __syncthreads();

    int warp = (blockIdx.x * blockDim.x + tid) >> 5;
    int l = tid & 31;
    if (warp >= NN) return;
    int n = warp;
    const int* cs = g_cs8 + t * (NN + 1);
    int s = cs[n], e = cs[n + 1];
    const int* er = g_erow8 + (size_t)t * EE;
    const float* en = g_enorm8 + (size_t)t * EE;
    const float4* V4 = (const float4*)V2src;

    float4 acc = make_float4(0.f, 0.f, 0.f, 0.f);
    for (int base = s; base < e; base += 32) {
        int cnt = e - base; if (cnt > 32) cnt = 32;
        int r = (l < cnt) ? er[base + l] : 0;
        float w = (l < cnt) ? en[base + l] : 0.0f;
#pragma unroll 4
        for (int j = 0; j < cnt; j++) {
            int rj = __shfl_sync(0xffffffffu, r, j);
            float wj = __shfl_sync(0xffffffffu, w, j);
            float4 v = V4[(size_t)rj * 32 + l];
            acc = f4fma(wj, v, acc);
        }
    }
    // dense: Y1 + H@A1 + 2*acc
    float h = g_H[(size_t)n * 32 + l];
    float4 d = make_float4(0.f, 0.f, 0.f, 0.f);
    const float4* A4 = (const float4*)sA1;
#pragma unroll
    for (int k = 0; k < 32; k++) {
        float hk = __shfl_sync(0xffffffffu, h, k);
        d = f4fma(hk, A4[k * 32 + l], d);
    }
    float4 y = ((const float4*)g_Y1)[(size_t)n * 32 + l];
    float4 outv = make_float4(y.x + d.x + 2.0f * acc.x,
                              y.y + d.y + 2.0f * acc.y,
                              y.z + d.z + 2.0f * acc.z,
                              y.w + d.w + 2.0f * acc.w);
    ((float4*)g_V1)[(size_t)n * 32 + l] = outv;
}

// Kernel B: U1 = L @ V1 ; PRE = Z0 + H@A0 + U1 ; gates -> H',C' ;
//           V2' = Y2 + H'@A2 (skipped on last step)
__global__ void stepB(int t, const float* __restrict__ wc, int last) {
    __shared__ float sA0[32 * 128];
    __shared__ float sA2[32 * 128];
    int tid = threadIdx.x;
    for (int i = tid; i < 32 * 128; i += 256) { sA0[i] = g_A0[i]; sA2[i] = g_A2[i]; }
    __syncthreads();

    int warp = (blockIdx.x * blockDim.x + tid) >> 5;
    int l = tid & 31;
    if (warp >= NN) return;
    int n = warp;
    const int* cs = g_cs8 + t * (NN + 1);
    int s = cs[n], e = cs[n + 1];
    const int* er = g_erow8 + (size_t)t * EE;
    const float* en = g_enorm8 + (size_t)t * EE;
    const float4* V4 = (const float4*)g_V1;

    float4 acc = make_float4(0.f, 0.f, 0.f, 0.f);
    for (int base = s; base < e; base += 32) {
        int cnt = e - base; if (cnt > 32) cnt = 32;
        int r = (l < cnt) ? er[base + l] : 0;
        float w = (l < cnt) ? en[base + l] : 0.0f;
#pragma unroll 4
        for (int j = 0; j < cnt; j++) {
            int rj = __shfl_sync(0xffffffffu, r, j);
            float wj = __shfl_sync(0xffffffffu, w, j);
            float4 v = V4[(size_t)rj * 32 + l];
            acc = f4fma(wj, v, acc);
        }
    }
    float h = g_H[(size_t)n * 32 + l];
    float4 d = make_float4(0.f, 0.f, 0.f, 0.f);
    const float4* A04 = (const float4*)sA0;
#pragma unroll
    for (int k = 0; k < 32; k++) {
        float hk = __shfl_sync(0xffffffffu, h, k);
        d = f4fma(hk, A04[k * 32 + l], d);
    }
    float4 z = ((const float4*)g_Z0)[(size_t)n * 32 + l];
    // pre-acts for hidden unit l: (i, f, c, o)
    float pi = z.x + d.x + acc.x;
    float pf = z.y + d.y + acc.y;
    float pc = z.z + d.z + acc.z;
    float po = z.w + d.w + acc.w;

    float Cs = g_C[(size_t)n * 32 + l];
    float ig = sigm(pi + wc[l] * Cs);
    float fg = sigm(pf + wc[32 + l] * Cs);
    float Cn = fg * Cs + ig * tanhf(pc);
    float og = sigm(po + wc[64 + l] * Cn);
    float Hn = og * tanhf(Cn);
    g_C[(size_t)n * 32 + l] = Cn;
    g_H[(size_t)n * 32 + l] = Hn;

    if (!last) {
        float4 d2 = make_float4(0.f, 0.f, 0.f, 0.f);
        const float4* A24 = (const float4*)sA2;
#pragma unroll
        for (int k = 0; k < 32; k++) {
            float hk = __shfl_sync(0xffffffffu, Hn, k);
            d2 = f4fma(hk, A24[k * 32 + l], d2);
        }
        float4 y2 = ((const float4*)g_Y2)[(size_t)n * 32 + l];
        ((float4*)g_V2)[(size_t)n * 32 + l] = f4add(y2, d2);
    }
}

// ---------------- head -------------------------------------------------------
__global__ void h1_kernel(const float* __restrict__ w, const float* __restrict__ b) {
    int idx = blockIdx.x * blockDim.x + threadIdx.x;
    if (idx < NN * 16) {
        int n = idx >> 4, o = idx & 15;
        float s = b[o];
        const float* hr = g_H + (size_t)n * 32;
#pragma unroll
        for (int k = 0; k < 32; k++) {
            float hv = hr[k];
            hv = hv > 0.0f ? hv : 0.0f;
            s += hv * w[k * 16 + o];
        }
        g_h1[idx] = s > 0.0f ? s : 0.0f;
    }
}

__global__ void pair_kernel(const int* __restrict__ src, const int* __restrict__ dst,
                            const float* __restrict__ fc2w, const float* __restrict__ fc2b,
                            const float* __restrict__ fc3w, const float* __restrict__ fc3b,
                            const float* __restrict__ bfw, const float* __restrict__ bfb,
                            float* __restrict__ out) {
    __shared__ float sw2[512], sb2[16], sw3[128], sb3[8], swb[8];
    __shared__ float sbb;
    int t = threadIdx.x;
    sw2[t] = fc2w[t];
    sw2[t + 256] = fc2w[t + 256];
    if (t < 128) sw3[t] = fc3w[t];
    if (t < 16) sb2[t] = fc2b[t];
    if (t < 8) { sb3[t] = fc3b[t]; swb[t] = bfw[t]; }
    if (t == 0) sbb = bfb[0];
    __syncthreads();

    int p = blockIdx.x * blockDim.x + t;
    if (p >= PP) return;
    int s = src[p], d = dst[p];
    float a[16], bb[16];
    const float4* ap = (const float4*)(g_h1 + (size_t)s * 16);
    const float4* bp = (const float4*)(g_h1 + (size_t)d * 16);
#pragma unroll
    for (int i = 0; i < 4; i++) {
        float4 va = ap[i], vb = bp[i];
        a[i * 4 + 0] = va.x; a[i * 4 + 1] = va.y; a[i * 4 + 2] = va.z; a[i * 4 + 3] = va.w;
        bb[i * 4 + 0] = vb.x; bb[i * 4 + 1] = vb.y; bb[i * 4 + 2] = vb.z; bb[i * 4 + 3] = vb.w;
    }
    float v2[16];
#pragma unroll
    for (int j = 0; j < 16; j++) {
        float acc = sb2[j];
#pragma unroll
        for (int k = 0; k < 16; k++) acc += a[k] * sw2[k * 16 + j];
#pragma unroll
        for (int k = 0; k < 16; k++) acc += bb[k] * sw2[(16 + k) * 16 + j];
        v2[j] = acc > 0.0f ? acc : 0.0f;
    }
    float v3[8];
#pragma unroll
    for (int j = 0; j < 8; j++) {
        float acc = sb3[j];
#pragma unroll
        for (int k = 0; k < 16; k++) acc += v2[k] * sw3[k * 8 + j];
        v3[j] = acc > 0.0f ? acc : 0.0f;
    }
    float acc = sbb;
#pragma unroll
    for (int j = 0; j < 8; j++) acc += v3[j] * swb[j];
    out[p] = 1.0f / (1.0f + expf(-acc));
}

// ---------------------------------------------------------------------------
extern "C" void kernel_launch(void* const* d_in, const int* in_sizes, int n_in,
                              void* d_out, int out_size) {
    const float* x    = (const float*)d_in[0];
    const int*   eidx = (const int*)d_in[1];
    const int*   src  = (const int*)d_in[2];
    const int*   dst  = (const int*)d_in[3];
    const float* Wx   = (const float*)d_in[4];
    const float* bx   = (const float*)d_in[5];
    const float* Wh   = (const float*)d_in[6];
    const float* bh   = (const float*)d_in[7];
    const float* bg   = (const float*)d_in[8];
    const float* wc   = (const float*)d_in[9];
    const float* fc1w = (const float*)d_in[10];
    const float* fc1b = (const float*)d_in[11];
    const float* fc2w = (const float*)d_in[12];
    const float* fc2b = (const float*)d_in[13];
    const float* fc3w = (const float*)d_in[14];
    const float* fc3b = (const float*)d_in[15];
    const float* bfw  = (const float*)d_in[16];
    const float* bfb  = (const float*)d_in[17];
    float* out = (float*)d_out;

    (void)in_sizes; (void)n_in; (void)out_size;

    // ---- weight folding + state init ----
    build_weights<<<(12288 + 3 * 8192 + 128 + 255) / 256, 256>>>(Wx, bx, Wh, bh, bg);
    zero_state<<<(TT * NN + 255) / 256, 256>>>();

    // ---- CSC build for all 8 snapshots ----
    long long tot = (long long)TT * EE;
    histogram8<<<(int)((tot + 255) / 256), 256>>>(eidx);
    dis8_kernel<<<(TT * NN + 255) / 256, 256>>>();
    scan8<<<TT, 1024>>>();
    scatter8<<<(int)((tot + 255) / 256), 256>>>(eidx);

    // ---- init dense: Y1, Y2, Z0 ----
    int gb = (NN + 63) / 64;
    gemm_init<<<gb, 256>>>(x, g_W1p, nullptr, g_Y1);
    gemm_init<<<gb, 256>>>(x, g_W2p, nullptr, g_Y2);
    gemm_init<<<gb, 256>>>(x, g_W03p, g_biasp, g_Z0);

    // ---- recurrent loop: 2 fused kernels per step ----
    int sg = (NN * 32 + 255) / 256;
    for (int t = 0; t < TT; t++) {
        const float* v2src = (t == 0) ? g_Y2 : g_V2;
        stepA<<<sg, 256>>>(t, v2src);
        stepB<<<sg, 256>>>(t, wc, (t == TT - 1) ? 1 : 0);
    }

    // ---- head ----
    h1_kernel<<<(NN * 16 + 255) / 256, 256>>>(fc1w, fc1b);
    pair_kernel<<<(PP + 255) / 256, 256>>>(src, dst, fc2w, fc2b, fc3w, fc3b, bfw, bfb, out);
}

// round 8
// speedup vs baseline: 1.0082x; 1.0082x over previous
#include <cuda_runtime.h>

#define NN 50000
#define FF 64
#define HIDN 32
#define TT 8
#define EE 800000
#define PP 800000

// ---------------- persistent scratch (static device arrays) ------------------
// All N x 128 tensors use gate-permuted column layout: col = h*4 + g
// so a float4 at h*4 holds (i,f,c,o) pre-acts / weights for hidden unit h.
__device__ float g_Y1[(size_t)NN * 128];
__device__ float g_Y2[(size_t)NN * 128];
__device__ float g_Z0[(size_t)NN * 128];
__device__ float g_V1[(size_t)NN * 128];
__device__ float g_V2[(size_t)NN * 128];
__device__ float g_H[(size_t)NN * 32];
__device__ float g_C[(size_t)NN * 32];
__device__ float g_h1[(size_t)NN * 16];

__device__ int   g_deg8[TT * NN];
__device__ int   g_hist8[TT * NN];
__device__ int   g_fill8[TT * NN];
__device__ int   g_cs8[TT * (NN + 1)];
__device__ float g_dis8[TT * NN];
__device__ int2  g_epack8[(size_t)TT * EE];   // {row, bitcast(norm)} per CSC slot

// folded weights (gate-permuted columns)
__device__ float g_A0[32 * 128];   // Wh0 - Wh2
__device__ float g_A1[32 * 128];   // Wh1
__device__ float g_A2[32 * 128];   // Wh2
__device__ float g_W03p[64 * 128]; // Wx0 - Wx2
__device__ float g_W1p[64 * 128];  // Wx1
__device__ float g_W2p[64 * 128];  // Wx2
__device__ float g_biasp[128];     // bx + bh + b_gate

__device__ __forceinline__ float sigm(float v) { return 1.0f / (1.0f + expf(-v)); }

__device__ __forceinline__ float4 f4add(float4 a, float4 b) {
    return make_float4(a.x + b.x, a.y + b.y, a.z + b.z, a.w + b.w);
}
__device__ __forceinline__ float4 f4fma(float s, float4 a, float4 acc) {
    acc.x += s * a.x; acc.y += s * a.y; acc.z += s * a.z; acc.w += s * a.w;
    return acc;
}

// ---------------- weight folding --------------------------------------------
__global__ void build_weights(const float* __restrict__ Wx, const float* __restrict__ bx,
                              const float* __restrict__ Wh, const float* __restrict__ bh,
                              const float* __restrict__ bg) {
    int idx = blockIdx.x * blockDim.x + threadIdx.x;
    if (idx < 12288) {                         // A0 / A1 / A2 : 32 x 128 each
        int m = idx >> 12;                     // which matrix
        int r = (idx >> 7) & 31;               // k row
        int c = idx & 127;
        int h = c >> 2, g = c & 3;
        float v;
        if (m == 0)      v = Wh[((g * 3 + 0) * 32 + r) * 32 + h]
                           - Wh[((g * 3 + 2) * 32 + r) * 32 + h];
        else if (m == 1) v = Wh[((g * 3 + 1) * 32 + r) * 32 + h];
        else             v = Wh[((g * 3 + 2) * 32 + r) * 32 + h];
        if (m == 0) g_A0[(idx & 4095)] = v;
        else if (m == 1) g_A1[(idx & 4095)] = v;
        else g_A2[(idx & 4095)] = v;
    } else if (idx < 12288 + 3 * 8192) {       // W03p / W1p / W2p : 64 x 128
        int base = idx - 12288;
        int m = base >> 13;
        int f = (base >> 7) & 63;
        int c = base & 127;
        int h = c >> 2, g = c & 3;
        float v;
        if (m == 0)      v = Wx[((g * 3 + 0) * 64 + f) * 32 + h]
                           - Wx[((g * 3 + 2) * 64 + f) * 32 + h];
        else if (m == 1) v = Wx[((g * 3 + 1) * 64 + f) * 32 + h];
        else             v = Wx[((g * 3 + 2) * 64 + f) * 32 + h];
        int o = f * 128 + c;
        if (m == 0) g_W03p[o] = v;
        else if (m == 1) g_W1p[o] = v;
        else g_W2p[o] = v;
    } else if (idx < 12288 + 3 * 8192 + 128) { // biasp
        int c = idx - 12288 - 3 * 8192;
        int h = c >> 2, g = c & 3;
        g_biasp[c] = bx[g * 32 + h] + bh[g * 32 + h] + bg[g * 32 + h];
    }
}

__global__ void zero_state() {
    int idx = blockIdx.x * blockDim.x + threadIdx.x;
    if (idx < NN * 32) { g_H[idx] = 0.0f; g_C[idx] = 0.0f; }
    if (idx < TT * NN) { g_deg8[idx] = 0; g_hist8[idx] = 0; g_fill8[idx] = 0; }
}

// ---------------- CSC build for all 8 snapshots ------------------------------
__global__ void histogram8(const int* __restrict__ eidx) {
    long long i = (long long)blockIdx.x * blockDim.x + threadIdx.x;
    if (i < (long long)TT * EE) {
        int t = (int)(i / EE), e = (int)(i % EE);
        const int* row = eidx + (size_t)t * 2 * EE;
        const int* col = row + EE;
        atomicAdd(&g_deg8[t * NN + row[e]], 1);
        atomicAdd(&g_hist8[t * NN + col[e]], 1);
    }
}

__global__ void dis8_kernel() {
    int i = blockIdx.x * blockDim.x + threadIdx.x;
    if (i < TT * NN) {
        int d = g_deg8[i];
        g_dis8[i] = (d > 0) ? rsqrtf((float)d) : 0.0f;
    }
}

// one block per step; scans its 50000-entry histogram
__global__ void scan8() {
    __shared__ int sh[1024];
    __shared__ int stotal;
    int t = blockIdx.x;
    const int* hist = g_hist8 + t * NN;
    int* cs = g_cs8 + t * (NN + 1);
    int tid = threadIdx.x;
    if (tid == 0) stotal = 0;
    __syncthreads();
    for (int base = 0; base < NN; base += 1024) {
        int i = base + tid;
        int v = (i < NN) ? hist[i] : 0;
        sh[tid] = v;
        __syncthreads();
        for (int off = 1; off < 1024; off <<= 1) {
            int tv = 0;
            if (tid >= off) tv = sh[tid - off];
            __syncthreads();
            sh[tid] += tv;
            __syncthreads();
        }
        if (i < NN) cs[i] = stotal + sh[tid] - v;
        __syncthreads();
        if (tid == 0) stotal += sh[1023];
        __syncthreads();
    }
    if (tid == 0) cs[NN] = stotal;
}

__global__ void scatter8(const int* __restrict__ eidx) {
    long long i = (long long)blockIdx.x * blockDim.x + threadIdx.x;
    if (i < (long long)TT * EE) {
        int t = (int)(i / EE), e = (int)(i % EE);
        const int* row = eidx + (size_t)t * 2 * EE;
        const int* col = row + EE;
        int r = row[e], c = col[e];
        int pos = g_cs8[t * (NN + 1) + c] + atomicAdd(&g_fill8[t * NN + c], 1);
        float nrm = -g_dis8[t * NN + r] * g_dis8[t * NN + c];
        g_epack8[(size_t)t * EE + pos] = make_int2(r, __float_as_int(nrm));
    }
}

// ---------------- init GEMM: out[N,128] = x[N,64] @ Bw[64,128] (+bias) -------
__global__ void gemm_init(const float* __restrict__ x, const float* __restrict__ Bw,
                          const float* __restrict__ bias, float* __restrict__ out) {
    __shared__ float As[8][64];
    __shared__ float Bs[8][128];
    int bm = blockIdx.x * 64;
    int tid = threadIdx.x;
    int tcol = tid & 15;
    int trow = tid >> 4;
    float acc[4][8];
#pragma unroll
    for (int i = 0; i < 4; i++)
#pragma unroll
        for (int j = 0; j < 8; j++) acc[i][j] = 0.0f;

    for (int k0 = 0; k0 < 64; k0 += 8) {
#pragma unroll
        for (int i = 0; i < 2; i++) {
            int idx = tid + i * 256;
            int m = idx >> 3, k = idx & 7;
            int row = bm + m;
            As[k][m] = (row < NN) ? x[(size_t)row * 64 + k0 + k] : 0.0f;
        }
#pragma unroll
        for (int i = 0; i < 4; i++) {
            int idx = tid + i * 256;
            int k = idx >> 7, n = idx & 127;
            Bs[k][n] = Bw[(size_t)(k0 + k) * 128 + n];
        }
        __syncthreads();
#pragma unroll
        for (int k = 0; k < 8; k++) {
            float a[4], b[8];
#pragma unroll
            for (int i = 0; i < 4; i++) a[i] = As[k][trow * 4 + i];
#pragma unroll
            for (int j = 0; j < 8; j++) b[j] = Bs[k][tcol * 8 + j];
#pragma unroll
            for (int i = 0; i < 4; i++)
#pragma unroll
                for (int j = 0; j < 8; j++) acc[i][j] += a[i] * b[j];
        }
        __syncthreads();
    }
#pragma unroll
    for (int i = 0; i < 4; i++) {
        int row = bm + trow * 4 + i;
        if (row < NN) {
#pragma unroll
            for (int j = 0; j < 8; j++) {
                int n = tcol * 8 + j;
                float v = acc[i][j];
                if (bias) v += bias[n];
                out[(size_t)row * 128 + n] = v;
            }
        }
    }
}

// ---------------- fused step kernels -----------------------------------------
// Gather loop (R2-proven pattern): per edge, one 8B warp-broadcast load of
// {row, norm} + one coalesced 128B-row LDG.128; unroll 8 for MLP.
// Kernel A: U2 = L @ V2src ; V1 = Y1 + H@A1 + 2*U2
__global__ void stepA(int t, const float* __restrict__ V2src) {
    __shared__ float sA1[32 * 128];
    int tid = threadIdx.x;
    for (int i = tid; i < 32 * 128; i += 256) sA1[i] = g_A1[i];
    __syncthreads();

    int warp = (blockIdx.x * blockDim.x + tid) >> 5;
    int l = tid & 31;
    if (warp >= NN) return;
    int n = warp;
    const int* cs = g_cs8 + t * (NN + 1);
    int s = cs[n], e = cs[n + 1];
    const int2* __restrict__ ep = g_epack8 + (size_t)t * EE;
    const float4* __restrict__ V4 = (const float4*)V2src;

    float4 acc = make_float4(0.f, 0.f, 0.f, 0.f);
#pragma unroll 8
    for (int i = s; i < e; i++) {
        int2 p = ep[i];                       // warp-broadcast 8B load
        float w = __int_as_float(p.y);
        float4 v = V4[(size_t)p.x * 32 + l];  // coalesced 512B row
        acc = f4fma(w, v, acc);
    }
    // dense: Y1 + H@A1 + 2*acc
    float h = g_H[(size_t)n * 32 + l];
    float4 d = make_float4(0.f, 0.f, 0.f, 0.f);
    const float4* A4 = (const float4*)sA1;
#pragma unroll
    for (int k = 0; k < 32; k++) {
        float hk = __shfl_sync(0xffffffffu, h, k);
        d = f4fma(hk, A4[k * 32 + l], d);
    }
    float4 y = ((const float4*)g_Y1)[(size_t)n * 32 + l];
    float4 outv = make_float4(y.x + d.x + 2.0f * acc.x,
                              y.y + d.y + 2.0f * acc.y,
                              y.z + d.z + 2.0f * acc.z,
                              y.w + d.w + 2.0f * acc.w);
    ((float4*)g_V1)[(size_t)n * 32 + l] = outv;
}

// Kernel B: U1 = L @ V1 ; PRE = Z0 + H@A0 + U1 ; gates -> H',C' ;
//           V2' = Y2 + H'@A2 (skipped on last step)
__global__ void stepB(int t, const float* __restrict__ wc, int last) {
    __shared__ float sA0[32 * 128];
    __shared__ float sA2[32 * 128];
    int tid = threadIdx.x;
    for (int i = tid; i < 32 * 128; i += 256) { sA0[i] = g_A0[i]; sA2[i] = g_A2[i]; }
    __syncthreads();

    int warp = (blockIdx.x * blockDim.x + tid) >> 5;
    int l = tid & 31;
    if (warp >= NN) return;
    int n = warp;
    const int* cs = g_cs8 + t * (NN + 1);
    int s = cs[n], e = cs[n + 1];
    const int2* __restrict__ ep = g_epack8 + (size_t)t * EE;
    const float4* __restrict__ V4 = (const float4*)g_V1;

    float4 acc = make_float4(0.f, 0.f, 0.f, 0.f);
#pragma unroll 8
    for (int i = s; i < e; i++) {
        int2 p = ep[i];
        float w = __int_as_float(p.y);
        float4 v = V4[(size_t)p.x * 32 + l];
        acc = f4fma(w, v, acc);
    }
    float h = g_H[(size_t)n * 32 + l];
    float4 d = make_float4(0.f, 0.f, 0.f, 0.f);
    const float4* A04 = (const float4*)sA0;
#pragma unroll
    for (int k = 0; k < 32; k++) {
        float hk = __shfl_sync(0xffffffffu, h, k);
        d = f4fma(hk, A04[k * 32 + l], d);
    }
    float4 z = ((const float4*)g_Z0)[(size_t)n * 32 + l];
    // pre-acts for hidden unit l: (i, f, c, o)
    float pi = z.x + d.x + acc.x;
    float pf = z.y + d.y + acc.y;
    float pc = z.z + d.z + acc.z;
    float po = z.w + d.w + acc.w;

    float Cs = g_C[(size_t)n * 32 + l];
    float ig = sigm(pi + wc[l] * Cs);
    float fg = sigm(pf + wc[32 + l] * Cs);
    float Cn = fg * Cs + ig * tanhf(pc);
    float og = sigm(po + wc[64 + l] * Cn);
    float Hn = og * tanhf(Cn);
    g_C[(size_t)n * 32 + l] = Cn;
    g_H[(size_t)n * 32 + l] = Hn;

    if (!last) {
        float4 d2 = make_float4(0.f, 0.f, 0.f, 0.f);
        const float4* A24 = (const float4*)sA2;
#pragma unroll
        for (int k = 0; k < 32; k++) {
            float hk = __shfl_sync(0xffffffffu, Hn, k);
            d2 = f4fma(hk, A24[k * 32 + l], d2);
        }
        float4 y2 = ((const float4*)g_Y2)[(size_t)n * 32 + l];
        ((float4*)g_V2)[(size_t)n * 32 + l] = f4add(y2, d2);
    }
}

// ---------------- head -------------------------------------------------------
__global__ void h1_kernel(const float* __restrict__ w, const float* __restrict__ b) {
    int idx = blockIdx.x * blockDim.x + threadIdx.x;
    if (idx < NN * 16) {
        int n = idx >> 4, o = idx & 15;
        float s = b[o];
        const float* hr = g_H + (size_t)n * 32;
#pragma unroll
        for (int k = 0; k < 32; k++) {
            float hv = hr[k];
            hv = hv > 0.0f ? hv : 0.0f;
            s += hv * w[k * 16 + o];
        }
        g_h1[idx] = s > 0.0f ? s : 0.0f;
    }
}

__global__ void pair_kernel(const int* __restrict__ src, const int* __restrict__ dst,
                            const float* __restrict__ fc2w, const float* __restrict__ fc2b,
                            const float* __restrict__ fc3w, const float* __restrict__ fc3b,
                            const float* __restrict__ bfw, const float* __restrict__ bfb,
                            float* __restrict__ out) {
    __shared__ float sw2[512], sb2[16], sw3[128], sb3[8], swb[8];
    __shared__ float sbb;
    int t = threadIdx.x;
    sw2[t] = fc2w[t];
    sw2[t + 256] = fc2w[t + 256];
    if (t < 128) sw3[t] = fc3w[t];
    if (t < 16) sb2[t] = fc2b[t];
    if (t < 8) { sb3[t] = fc3b[t]; swb[t] = bfw[t]; }
    if (t == 0) sbb = bfb[0];
    __syncthreads();

    int p = blockIdx.x * blockDim.x + t;
    if (p >= PP) return;
    int s = src[p], d = dst[p];
    float a[16], bb[16];
    const float4* ap = (const float4*)(g_h1 + (size_t)s * 16);
    const float4* bp = (const float4*)(g_h1 + (size_t)d * 16);
#pragma unroll
    for (int i = 0; i < 4; i++) {
        float4 va = ap[i], vb = bp[i];
        a[i * 4 + 0] = va.x; a[i * 4 + 1] = va.y; a[i * 4 + 2] = va.z; a[i * 4 + 3] = va.w;
        bb[i * 4 + 0] = vb.x; bb[i * 4 + 1] = vb.y; bb[i * 4 + 2] = vb.z; bb[i * 4 + 3] = vb.w;
    }
    float v2[16];
#pragma unroll
    for (int j = 0; j < 16; j++) {
        float acc = sb2[j];
#pragma unroll
        for (int k = 0; k < 16; k++) acc += a[k] * sw2[k * 16 + j];
#pragma unroll
        for (int k = 0; k < 16; k++) acc += bb[k] * sw2[(16 + k) * 16 + j];
        v2[j] = acc > 0.0f ? acc : 0.0f;
    }
    float v3[8];
#pragma unroll
    for (int j = 0; j < 8; j++) {
        float acc = sb3[j];
#pragma unroll
        for (int k = 0; k < 16; k++) acc += v2[k] * sw3[k * 8 + j];
        v3[j] = acc > 0.0f ? acc : 0.0f;
    }
    float acc = sbb;
#pragma unroll
    for (int j = 0; j < 8; j++) acc += v3[j] * swb[j];
    out[p] = 1.0f / (1.0f + expf(-acc));
}

// ---------------------------------------------------------------------------
extern "C" void kernel_launch(void* const* d_in, const int* in_sizes, int n_in,
                              void* d_out, int out_size) {
    const float* x    = (const float*)d_in[0];
    const int*   eidx = (const int*)d_in[1];
    const int*   src  = (const int*)d_in[2];
    const int*   dst  = (const int*)d_in[3];
    const float* Wx   = (const float*)d_in[4];
    const float* bx   = (const float*)d_in[5];
    const float* Wh   = (const float*)d_in[6];
    const float* bh   = (const float*)d_in[7];
    const float* bg   = (const float*)d_in[8];
    const float* wc   = (const float*)d_in[9];
    const float* fc1w = (const float*)d_in[10];
    const float* fc1b = (const float*)d_in[11];
    const float* fc2w = (const float*)d_in[12];
    const float* fc2b = (const float*)d_in[13];
    const float* fc3w = (const float*)d_in[14];
    const float* fc3b = (const float*)d_in[15];
    const float* bfw  = (const float*)d_in[16];
    const float* bfb  = (const float*)d_in[17];
    float* out = (float*)d_out;

    (void)in_sizes; (void)n_in; (void)out_size;

    // ---- weight folding + state init ----
    build_weights<<<(12288 + 3 * 8192 + 128 + 255) / 256, 256>>>(Wx, bx, Wh, bh, bg);
    zero_state<<<(TT * NN + 255) / 256, 256>>>();

    // ---- CSC build for all 8 snapshots ----
    long long tot = (long long)TT * EE;
    histogram8<<<(int)((tot + 255) / 256), 256>>>(eidx);
    dis8_kernel<<<(TT * NN + 255) / 256, 256>>>();
    scan8<<<TT, 1024>>>();
    scatter8<<<(int)((tot + 255) / 256), 256>>>(eidx);

    // ---- init dense: Y1, Y2, Z0 ----
    int gb = (NN + 63) / 64;
    gemm_init<<<gb, 256>>>(x, g_W1p, nullptr, g_Y1);
    gemm_init<<<gb, 256>>>(x, g_W2p, nullptr, g_Y2);
    gemm_init<<<gb, 256>>>(x, g_W03p, g_biasp, g_Z0);

    // ---- recurrent loop: 2 fused kernels per step ----
    int sg = (NN * 32 + 255) / 256;
    for (int t = 0; t < TT; t++) {
        const float* v2src = (t == 0) ? g_Y2 : g_V2;
        stepA<<<sg, 256>>>(t, v2src);
        stepB<<<sg, 256>>>(t, wc, (t == TT - 1) ? 1 : 0);
    }

    // ---- head ----
    h1_kernel<<<(NN * 16 + 255) / 256, 256>>>(fc1w, fc1b);
    pair_kernel<<<(PP + 255) / 256, 256>>>(src, dst, fc2w, fc2b, fc3w, fc3b, bfw, bfb, out);
}

// round 10
// speedup vs baseline: 9.5060x; 9.4291x over previous
#include <cuda_runtime.h>

#define NN 50000
#define FF 64
#define HIDN 32
#define TT 8
#define EE 800000
#define PP 800000

// ---------------- persistent scratch (static device arrays) ------------------
__device__ float g_ACAT[(size_t)NN * 224];   // [tx1(64) | u=L tx1(64) | H(32) | th1(32) | uh(32)]
__device__ float g_Z0[(size_t)NN * 128];     // x@(Wx0-Wx2) + (bx+bh+b_gate)
__device__ float g_PRE[(size_t)NN * 128];    // gate preactivations
__device__ float g_TX1[(size_t)NN * 64];
__device__ float g_TH1[(size_t)NN * 32];
__device__ float g_H[(size_t)NN * 32];
__device__ float g_C[(size_t)NN * 32];
__device__ float g_h1[(size_t)NN * 16];

__device__ int   g_deg8[TT * NN];
__device__ int   g_hist8[TT * NN];
__device__ int   g_fill8[TT * NN];
__device__ int   g_cs8[TT * (NN + 1)];
__device__ float g_dis8[TT * NN];
__device__ int   g_erow8[(size_t)TT * EE];
__device__ float g_enorm8[(size_t)TT * EE];

__device__ float g_B[224 * 128];
__device__ float g_W03[64 * 128];
__device__ float g_biasT[128];

__device__ __forceinline__ float sigm(float v) { return 1.0f / (1.0f + expf(-v)); }

// ---------------- weight folding (verbatim R2) -------------------------------
// B rows: [0:64)=Wx1  [64:128)=2*Wx2  [128:160)=Wh0-Wh2  [160:192)=Wh1  [192:224)=2*Wh2
__global__ void build_weights(const float* __restrict__ Wx, const float* __restrict__ bx,
                              const float* __restrict__ Wh, const float* __restrict__ bh,
                              const float* __restrict__ bg) {
    int idx = blockIdx.x * blockDim.x + threadIdx.x;
    const int NB = 224 * 128;
    if (idx < NB) {
        int r = idx >> 7, j = idx & 127;
        int g = j >> 5, h = j & 31;
        float v;
        if (r < 64)        v = Wx[((g * 3 + 1) * 64 + r) * 32 + h];
        else if (r < 128)  v = 2.0f * Wx[((g * 3 + 2) * 64 + (r - 64)) * 32 + h];
        else if (r < 160)  v = Wh[((g * 3 + 0) * 32 + (r - 128)) * 32 + h]
                             - Wh[((g * 3 + 2) * 32 + (r - 128)) * 32 + h];
        else if (r < 192)  v = Wh[((g * 3 + 1) * 32 + (r - 160)) * 32 + h];
        else               v = 2.0f * Wh[((g * 3 + 2) * 32 + (r - 192)) * 32 + h];
        g_B[idx] = v;
    } else if (idx < NB + 64 * 128) {
        int k = idx - NB;
        int f = k >> 7, j = k & 127;
        int g = j >> 5, h = j & 31;
        g_W03[k] = Wx[((g * 3 + 0) * 64 + f) * 32 + h] - Wx[((g * 3 + 2) * 64 + f) * 32 + h];
    } else if (idx < NB + 64 * 128 + 128) {
        int j = idx - NB - 64 * 128;
        g_biasT[j] = bx[j] + bh[j] + bg[j];
    }
}

__global__ void zero_state() {
    int idx = blockIdx.x * blockDim.x + threadIdx.x;
    if (idx < NN * HIDN) {
        g_H[idx] = 0.0f;
        g_C[idx] = 0.0f;
        int n = idx >> 5, h = idx & 31;
        g_ACAT[(size_t)n * 224 + 128 + h] = 0.0f;
    }
    if (idx < TT * NN) { g_deg8[idx] = 0; g_hist8[idx] = 0; g_fill8[idx] = 0; }
}

// ---------------- batched CSC build for all 8 snapshots ----------------------
__global__ void histogram8(const int* __restrict__ eidx) {
    long long i = (long long)blockIdx.x * blockDim.x + threadIdx.x;
    if (i < (long long)TT * EE) {
        int t = (int)(i / EE), e = (int)(i % EE);
        const int* row = eidx + (size_t)t * 2 * EE;
        const int* col = row + EE;
        atomicAdd(&g_deg8[t * NN + row[e]], 1);
        atomicAdd(&g_hist8[t * NN + col[e]], 1);
    }
}

__global__ void dis8_kernel() {
    int i = blockIdx.x * blockDim.x + threadIdx.x;
    if (i < TT * NN) {
        int d = g_deg8[i];
        g_dis8[i] = (d > 0) ? rsqrtf((float)d) : 0.0f;
    }
}

// one block per snapshot; scans its 50000-entry histogram
__global__ void scan8() {
    __shared__ int sh[1024];
    __shared__ int stotal;
    int t = blockIdx.x;
    const int* hist = g_hist8 + t * NN;
    int* cs = g_cs8 + t * (NN + 1);
    int tid = threadIdx.x;
    if (tid == 0) stotal = 0;
    __syncthreads();
    for (int base = 0; base < NN; base += 1024) {
        int i = base + tid;
        int v = (i < NN) ? hist[i] : 0;
        sh[tid] = v;
        __syncthreads();
        for (int off = 1; off < 1024; off <<= 1) {
            int tv = 0;
            if (tid >= off) tv = sh[tid - off];
            __syncthreads();
            sh[tid] += tv;
            __syncthreads();
        }
        if (i < NN) cs[i] = stotal + sh[tid] - v;
        __syncthreads();
        if (tid == 0) stotal += sh[1023];
        __syncthreads();
    }
    if (tid == 0) cs[NN] = stotal;
}

__global__ void scatter8(const int* __restrict__ eidx) {
    long long i = (long long)blockIdx.x * blockDim.x + threadIdx.x;
    if (i < (long long)TT * EE) {
        int t = (int)(i / EE), e = (int)(i % EE);
        const int* row = eidx + (size_t)t * 2 * EE;
        const int* col = row + EE;
        int r = row[e], c = col[e];
        int pos = g_cs8[t * (NN + 1) + c] + atomicAdd(&g_fill8[t * NN + c], 1);
        g_erow8[(size_t)t * EE + pos] = r;
        g_enorm8[(size_t)t * EE + pos] = -g_dis8[t * NN + r] * g_dis8[t * NN + c];
    }
}

// ---------------- gather (verbatim R2 body, + t indexing) --------------------
// one warp per destination node; gathers over incoming (CSC) edges.
// level 0: sources x (64) + H (32) -> TX1/TH1 + ACAT cols {0..63,160..191}
// level 1: sources TX1 + TH1      -> ACAT cols {64..127,192..223}
__global__ void gather_kernel(int t, const float* __restrict__ xsrc, int level) {
    int warp = (blockIdx.x * blockDim.x + threadIdx.x) >> 5;
    int lane = threadIdx.x & 31;
    if (warp >= NN) return;
    const int* cs = g_cs8 + t * (NN + 1);
    int s = cs[warp], e = cs[warp + 1];
    const int* __restrict__ er = g_erow8 + (size_t)t * EE;
    const float* __restrict__ en = g_enorm8 + (size_t)t * EE;
    const float* __restrict__ X = level ? g_TX1 : xsrc;
    const float* __restrict__ Hb = level ? g_TH1 : g_H;
    float a0 = 0.0f, a1 = 0.0f, ah = 0.0f;
#pragma unroll 4
    for (int i = s; i < e; i++) {
        int r = er[i];
        float w = en[i];
        a0 += w * X[(size_t)r * 64 + lane];
        a1 += w * X[(size_t)r * 64 + 32 + lane];
        ah += w * Hb[(size_t)r * 32 + lane];
    }
    float* acat = g_ACAT + (size_t)warp * 224;
    if (level == 0) {
        g_TX1[(size_t)warp * 64 + lane] = a0;
        g_TX1[(size_t)warp * 64 + 32 + lane] = a1;
        g_TH1[(size_t)warp * 32 + lane] = ah;
        acat[lane] = a0;
        acat[32 + lane] = a1;
        acat[160 + lane] = ah;
    } else {
        acat[64 + lane] = a0;
        acat[96 + lane] = a1;
        acat[192 + lane] = ah;
    }
}

// ---------------- GEMM (verbatim R2) -----------------------------------------
// mode 0: A=x (lda=64,K=64),  Bm=g_W03, init=g_biasT[col], out=g_Z0
// mode 1: A=g_ACAT (lda=224,K=224), Bm=g_B, init=g_Z0[row], out=g_PRE
__global__ void gemm128(const float* __restrict__ Aext, int mode) {
    const float* A; int lda, K; const float* Bm; float* Cout;
    if (mode == 0) { A = Aext;   lda = 64;  K = 64;  Bm = g_W03; Cout = g_Z0; }
    else           { A = g_ACAT; lda = 224; K = 224; Bm = g_B;   Cout = g_PRE; }

    __shared__ float As[8][64];
    __shared__ float Bs[8][128];
    int bm = blockIdx.x * 64;
    int tid = threadIdx.x;
    int tcol = tid & 15;
    int trow = tid >> 4;
    float acc[4][8];
#pragma unroll
    for (int i = 0; i < 4; i++)
#pragma unroll
        for (int j = 0; j < 8; j++) acc[i][j] = 0.0f;

    for (int k0 = 0; k0 < K; k0 += 8) {
#pragma unroll
        for (int i = 0; i < 2; i++) {
            int idx = tid + i * 256;
            int m = idx >> 3, k = idx & 7;
            int row = bm + m;
            As[k][m] = (row < NN) ? A[(size_t)row * lda + k0 + k] : 0.0f;
        }
#pragma unroll
        for (int i = 0; i < 4; i++) {
            int idx = tid + i * 256;
            int k = idx >> 7, n = idx & 127;
            Bs[k][n] = Bm[(size_t)(k0 + k) * 128 + n];
        }
        __syncthreads();
#pragma unroll
        for (int k = 0; k < 8; k++) {
            float a[4], b[8];
#pragma unroll
            for (int i = 0; i < 4; i++) a[i] = As[k][trow * 4 + i];
#pragma unroll
            for (int j = 0; j < 8; j++) b[j] = Bs[k][tcol * 8 + j];
#pragma unroll
            for (int i = 0; i < 4; i++)
#pragma unroll
                for (int j = 0; j < 8; j++) acc[i][j] += a[i] * b[j];
        }
        __syncthreads();
    }
#pragma unroll
    for (int i = 0; i < 4; i++) {
        int row = bm + trow * 4 + i;
        if (row < NN) {
#pragma unroll
            for (int j = 0; j < 8; j++) {
                int n = tcol * 8 + j;
                float v = acc[i][j];
                if (mode == 0) v += g_biasT[n];
                else           v += g_Z0[(size_t)row * 128 + n];
                Cout[(size_t)row * 128 + n] = v;
            }
        }
    }
}

__global__ void gates_kernel(const float* __restrict__ wc) {
    int idx = blockIdx.x * blockDim.x + threadIdx.x;
    if (idx < NN * HIDN) {
        int n = idx >> 5, h = idx & 31;
        const float* pre = g_PRE + (size_t)n * 128;
        float Cs = g_C[idx];
        float ig = sigm(pre[h]       + wc[h]      * Cs);
        float fg = sigm(pre[32 + h]  + wc[32 + h] * Cs);
        float ct = tanhf(pre[64 + h]);
        float Cn = fg * Cs + ig * ct;
        float og = sigm(pre[96 + h] + wc[64 + h] * Cn);
        float Hn = og * tanhf(Cn);
        g_C[idx] = Cn;
        g_H[idx] = Hn;
        g_ACAT[(size_t)n * 224 + 128 + h] = Hn;
    }
}

// ---------------- head (verbatim R2) -----------------------------------------
__global__ void h1_kernel(const float* __restrict__ w, const float* __restrict__ b) {
    int idx = blockIdx.x * blockDim.x + threadIdx.x;
    if (idx < NN * 16) {
        int n = idx >> 4, o = idx & 15;
        float s = b[o];
        const float* hr = g_H + (size_t)n * 32;
#pragma unroll
        for (int k = 0; k < 32; k++) {
            float hv = hr[k];
            hv = hv > 0.0f ? hv : 0.0f;
            s += hv * w[k * 16 + o];
        }
        g_h1[idx] = s > 0.0f ? s : 0.0f;
    }
}

__global__ void pair_kernel(const int* __restrict__ src, const int* __restrict__ dst,
                            const float* __restrict__ fc2w, const float* __restrict__ fc2b,
                            const float* __restrict__ fc3w, const float* __restrict__ fc3b,
                            const float* __restrict__ bfw, const float* __restrict__ bfb,
                            float* __restrict__ out) {
    __shared__ float sw2[512], sb2[16], sw3[128], sb3[8], swb[8];
    __shared__ float sbb;
    int t = threadIdx.x;
    sw2[t] = fc2w[t];
    sw2[t + 256] = fc2w[t + 256];
    if (t < 128) sw3[t] = fc3w[t];
    if (t < 16) sb2[t] = fc2b[t];
    if (t < 8) { sb3[t] = fc3b[t]; swb[t] = bfw[t]; }
    if (t == 0) sbb = bfb[0];
    __syncthreads();

    int p = blockIdx.x * blockDim.x + t;
    if (p >= PP) return;
    int s = src[p], d = dst[p];
    float a[16], bb[16];
    const float4* ap = (const float4*)(g_h1 + (size_t)s * 16);
    const float4* bp = (const float4*)(g_h1 + (size_t)d * 16);
#pragma unroll
    for (int i = 0; i < 4; i++) {
        float4 va = ap[i], vb = bp[i];
        a[i * 4 + 0] = va.x; a[i * 4 + 1] = va.y; a[i * 4 + 2] = va.z; a[i * 4 + 3] = va.w;
        bb[i * 4 + 0] = vb.x; bb[i * 4 + 1] = vb.y; bb[i * 4 + 2] = vb.z; bb[i * 4 + 3] = vb.w;
    }
    float v2[16];
#pragma unroll
    for (int j = 0; j < 16; j++) {
        float acc = sb2[j];
#pragma unroll
        for (int k = 0; k < 16; k++) acc += a[k] * sw2[k * 16 + j];
#pragma unroll
        for (int k = 0; k < 16; k++) acc += bb[k] * sw2[(16 + k) * 16 + j];
        v2[j] = acc > 0.0f ? acc : 0.0f;
    }
    float v3[8];
#pragma unroll
    for (int j = 0; j < 8; j++) {
        float acc = sb3[j];
#pragma unroll
        for (int k = 0; k < 16; k++) acc += v2[k] * sw3[k * 8 + j];
        v3[j] = acc > 0.0f ? acc : 0.0f;
    }
    float acc = sbb;
#pragma unroll
    for (int j = 0; j < 8; j++) acc += v3[j] * swb[j];
    out[p] = 1.0f / (1.0f + expf(-acc));
}

// ---------------------------------------------------------------------------
extern "C" void kernel_launch(void* const* d_in, const int* in_sizes, int n_in,
                              void* d_out, int out_size) {
    const float* x    = (const float*)d_in[0];
    const int*   eidx = (const int*)d_in[1];
    const int*   src  = (const int*)d_in[2];
    const int*   dst  = (const int*)d_in[3];
    const float* Wx   = (const float*)d_in[4];
    const float* bx   = (const float*)d_in[5];
    const float* Wh   = (const float*)d_in[6];
    const float* bh   = (const float*)d_in[7];
    const float* bg   = (const float*)d_in[8];
    const float* wc   = (const float*)d_in[9];
    const float* fc1w = (const float*)d_in[10];
    const float* fc1b = (const float*)d_in[11];
    const float* fc2w = (const float*)d_in[12];
    const float* fc2b = (const float*)d_in[13];
    const float* fc3w = (const float*)d_in[14];
    const float* fc3b = (const float*)d_in[15];
    const float* bfw  = (const float*)d_in[16];
    const float* bfb  = (const float*)d_in[17];
    float* out = (float*)d_out;

    (void)in_sizes; (void)n_in; (void)out_size;

    // ---- setup: weights, state, batched CSC for all 8 snapshots ----
    build_weights<<<(224 * 128 + 64 * 128 + 128 + 255) / 256, 256>>>(Wx, bx, Wh, bh, bg);
    zero_state<<<(NN * HIDN + 255) / 256, 256>>>();
    long long tot = (long long)TT * EE;
    histogram8<<<(int)((tot + 255) / 256), 256>>>(eidx);
    dis8_kernel<<<(TT * NN + 255) / 256, 256>>>();
    scan8<<<TT, 1024>>>();
    scatter8<<<(int)((tot + 255) / 256), 256>>>(eidx);

    // ---- Z0 = x@(Wx0-Wx2) + biases (once) ----
    gemm128<<<(NN + 63) / 64, 256>>>(x, 0);

    // ---- recurrent loop (R2 kernels, CSC build already done) ----
    for (int t = 0; t < TT; t++) {
        gather_kernel<<<(NN + 7) / 8, 256>>>(t, x, 0);
        gather_kernel<<<(NN + 7) / 8, 256>>>(t, x, 1);
        gemm128<<<(NN + 63) / 64, 256>>>(x, 1);
        gates_kernel<<<(NN * HIDN + 255) / 256, 256>>>(wc);
    }

    // ---- head ----
    h1_kernel<<<(NN * 16 + 255) / 256, 256>>>(fc1w, fc1b);
    pair_kernel<<<(PP + 255) / 256, 256>>>(src, dst, fc2w, fc2b, fc3w, fc3b, bfw, bfb, out);
}